// round 13
// baseline (speedup 1.0000x reference)
#include <cuda_runtime.h>
#include <math.h>

#define N 3072
#define H 256
#define NEDGE (N-1)
#define NREL 18
#define NB 64
#define NKB (N/NB)   // 48

// ---------------- device scratch (no allocations allowed) ----------------
__device__ float g_U[2*N*H];      // U_k = X @ W_bilin[k]
__device__ float g_hd[2*N];       // head scores per k
__device__ float g_dp[2*N];       // dep scores per k
__device__ float g_rs[N];         // root scores
__device__ float g_A[N*N];        // A = exp(c0)+exp(c1)
__device__ float g_M[N*N];        // permuted Laplacian -> LU in place
__device__ float g_colsum[N];     // off-diagonal column sums of A
__device__ double g_acc[3];       // 0: gold(edges), 1: ce, 2: log|det| sum
__device__ int g_neg;             // negative-pivot parity count
__device__ int g_bad;             // zero/nan/inf pivot flag

__device__ __forceinline__ float gelu_exact(float v){
    return 0.5f * v * (1.0f + erff(v * 0.70710678118654752f));
}

// ---------------- init ----------------
__global__ void k_init(){
    if(threadIdx.x == 0){
        g_acc[0]=0.0; g_acc[1]=0.0; g_acc[2]=0.0;
        g_neg=0; g_bad=0;
    }
}

// ---------------- U_k = X @ W_bilin[k]  (grid: (H/64, N/64, 2)) ----------------
__global__ __launch_bounds__(256) void k_computeU(const float* __restrict__ X,
                                                  const float* __restrict__ Wb){
    int kk = blockIdx.z;
    const float* W = Wb + kk*H*H;
    float* Uo = g_U + kk*N*H;
    __shared__ float As[32][65];   // [h][row]
    __shared__ float Bs[32][65];   // [h][col]
    int tid = threadIdx.x;
    int tx = tid & 15, ty = tid >> 4;
    int r0 = blockIdx.y*64, c0 = blockIdx.x*64;
    float acc[4][4];
#pragma unroll
    for(int i=0;i<4;i++)
#pragma unroll
        for(int j=0;j<4;j++) acc[i][j]=0.f;
    for(int h0=0; h0<H; h0+=32){
#pragma unroll
        for(int l=0;l<8;l++){
            int idx = l*256+tid;
            int i = idx>>5, t = idx&31;
            As[t][i] = X[(r0+i)*H + h0 + t];
        }
#pragma unroll
        for(int l=0;l<8;l++){
            int idx = l*256+tid;
            int t = idx>>6, c = idx&63;
            Bs[t][c] = W[(h0+t)*H + c0 + c];
        }
        __syncthreads();
#pragma unroll 8
        for(int t=0;t<32;t++){
            float a[4], b[4];
#pragma unroll
            for(int i=0;i<4;i++) a[i]=As[t][ty+16*i];
#pragma unroll
            for(int j=0;j<4;j++) b[j]=Bs[t][tx+16*j];
#pragma unroll
            for(int i=0;i<4;i++)
#pragma unroll
                for(int j=0;j<4;j++) acc[i][j] += a[i]*b[j];
        }
        __syncthreads();
    }
#pragma unroll
    for(int i=0;i<4;i++)
#pragma unroll
        for(int j=0;j<4;j++)
            Uo[(r0+ty+16*i)*H + c0+tx+16*j] = acc[i][j];
}

// ---------------- head/dep scores + root scores (grid: N blocks) ----------------
__global__ __launch_bounds__(256) void k_headdep(const float* __restrict__ X,
        const float* __restrict__ Wh, const float* __restrict__ Wd,
        const float* __restrict__ Wr1, const float* __restrict__ br1,
        const float* __restrict__ Wr2, const float* __restrict__ br2){
    int i = blockIdx.x, t = threadIdx.x;
    __shared__ float xs[H];
    __shared__ float red[256];
    xs[t] = X[i*H+t];
    __syncthreads();
    float acc = 0.f;
#pragma unroll 8
    for(int d=0; d<H; d++) acc += xs[d]*Wr1[d*H+t];
    acc += br1[t];
    float g = gelu_exact(acc);
    float vals[5];
    vals[0] = g*Wr2[t];
    vals[1] = xs[t]*Wh[t];
    vals[2] = xs[t]*Wh[H+t];
    vals[3] = xs[t]*Wd[t];
    vals[4] = xs[t]*Wd[H+t];
    float out[5];
#pragma unroll
    for(int v=0; v<5; v++){
        red[t]=vals[v]; __syncthreads();
        for(int s=128;s>0;s>>=1){ if(t<s) red[t]+=red[t+s]; __syncthreads(); }
        out[v]=red[0]; __syncthreads();
    }
    if(t==0){
        g_rs[i]   = out[0] + br2[0];
        g_hd[i]   = out[1];
        g_hd[N+i] = out[2];
        g_dp[i]   = out[3];
        g_dp[N+i] = out[4];
    }
}

// ---------------- A[i][j] = exp(c0)+exp(c1)  (grid: (N/64, N/64)) ----------------
__global__ __launch_bounds__(256) void k_compatA(const float* __restrict__ X,
                                                 const float* __restrict__ bb){
    __shared__ float U0s[32][65], U1s[32][65], Xs[32][65];
    int tid=threadIdx.x, tx=tid&15, ty=tid>>4;
    int r0=blockIdx.y*64, c0=blockIdx.x*64;
    float a0[4][4], a1[4][4];
#pragma unroll
    for(int i=0;i<4;i++)
#pragma unroll
        for(int j=0;j<4;j++){ a0[i][j]=0.f; a1[i][j]=0.f; }
    const float* U0 = g_U;
    const float* U1 = g_U + N*H;
    for(int d0=0; d0<H; d0+=32){
#pragma unroll
        for(int l=0;l<8;l++){
            int idx=l*256+tid; int i=idx>>5, t=idx&31;
            U0s[t][i] = U0[(r0+i)*H + d0+t];
            U1s[t][i] = U1[(r0+i)*H + d0+t];
            Xs[t][i]  = X [(c0+i)*H + d0+t];
        }
        __syncthreads();
#pragma unroll 8
        for(int t=0;t<32;t++){
            float x0[4],x1[4],b[4];
#pragma unroll
            for(int i=0;i<4;i++){ x0[i]=U0s[t][ty+16*i]; x1[i]=U1s[t][ty+16*i]; }
#pragma unroll
            for(int j=0;j<4;j++) b[j]=Xs[t][tx+16*j];
#pragma unroll
            for(int i=0;i<4;i++)
#pragma unroll
                for(int j=0;j<4;j++){ a0[i][j]+=x0[i]*b[j]; a1[i][j]+=x1[i]*b[j]; }
        }
        __syncthreads();
    }
    float bb0=bb[0], bb1=bb[1];
#pragma unroll
    for(int i=0;i<4;i++){
        int r = r0+ty+16*i;
        float h0=g_hd[r], h1=g_hd[N+r];
#pragma unroll
        for(int j=0;j<4;j++){
            int c = c0+tx+16*j;
            float c0v = a0[i][j] + bb0 + h0 + g_dp[c];
            float c1v = a1[i][j] + bb1 + h1 + g_dp[N+c];
            g_A[r*N+c] = expf(c0v) + expf(c1v);
        }
    }
}

// ---------------- off-diagonal column sums ----------------
__global__ void k_colsum(){
    int j = blockIdx.x*256 + threadIdx.x;
    float s = 0.f;
    for(int i=0;i<N;i++){
        if(i!=j) s += g_A[i*N+j];
    }
    g_colsum[j] = s;
}

// ---------------- build permuted Laplacian M (grid: (N/256, N)) ----------------
__global__ void k_buildM(){
    int j = blockIdx.x*256 + threadIdx.x;
    int i = blockIdx.y;
    int oi = (i==N-1) ? 0 : (i+1);
    int oj = (j==N-1) ? 0 : (j+1);
    float v;
    if(oi==0)          v = expf(g_rs[oj]);     // replaced row
    else if(oi==oj)    v = g_colsum[oj];       // exact off-diag column sum
    else               v = -g_A[oi*N+oj];
    g_M[i*N+j] = v;
}

// ---------------- gold: gather compat at edges ----------------
__global__ __launch_bounds__(256) void k_gold(const float* __restrict__ X,
        const float* __restrict__ Ladj, const float* __restrict__ Radj,
        const float* __restrict__ bb,
        const int* __restrict__ par, const int* __restrict__ chl){
    int e = blockIdx.x, t = threadIdx.x;
    int p = par[e], c = chl[e];
    __shared__ float red[256];
    float xc = X[c*H+t];
    float s0 = g_U[p*H+t]*xc;
    float s1 = g_U[N*H + p*H+t]*xc;
    red[t]=s0; __syncthreads();
    for(int s=128;s>0;s>>=1){ if(t<s) red[t]+=red[t+s]; __syncthreads(); }
    float r0v = red[0]; __syncthreads();
    red[t]=s1; __syncthreads();
    for(int s=128;s>0;s>>=1){ if(t<s) red[t]+=red[t+s]; __syncthreads(); }
    float r1v = red[0];
    if(t==0){
        float c0v = r0v + bb[0] + g_hd[p]   + g_dp[c];
        float c1v = r1v + bb[1] + g_hd[N+p] + g_dp[N+c];
        float lf = Ladj[(size_t)p*N+c];
        float rf = Radj[(size_t)p*N+c];
        atomicAdd(&g_acc[0], (double)(lf*c0v + rf*c1v));
    }
}

// ---------------- relation CE loss ----------------
__global__ __launch_bounds__(256) void k_ce(const float* __restrict__ X,
        const float* __restrict__ Wrel1, const float* __restrict__ brel1,
        const float* __restrict__ Wrel2, const float* __restrict__ brel2,
        const int* __restrict__ par, const int* __restrict__ chl,
        const int* __restrict__ rels){
    int e = blockIdx.x, t = threadIdx.x;
    int p = par[e], c = chl[e];
    __shared__ float xp[H], xc[H], hs[H];
    __shared__ float lg[NREL];
    xp[t] = X[p*H+t];
    xc[t] = X[c*H+t];
    __syncthreads();
    float acc = brel1[t];
#pragma unroll 8
    for(int d=0; d<H; d++) acc += xp[d]*Wrel1[d*H + t];
#pragma unroll 8
    for(int d=0; d<H; d++) acc += xc[d]*Wrel1[(H+d)*H + t];
    hs[t] = gelu_exact(acc);
    __syncthreads();
    if(t < NREL){
        float a = brel2[t];
        for(int u=0; u<H; u++) a += hs[u]*Wrel2[u*NREL + t];
        lg[t] = a;
    }
    __syncthreads();
    if(t==0){
        float mx = lg[0];
#pragma unroll
        for(int r=1;r<NREL;r++) mx = fmaxf(mx, lg[r]);
        float s = 0.f;
#pragma unroll
        for(int r=0;r<NREL;r++) s += expf(lg[r]-mx);
        float lse = mx + logf(s);
        int rl = rels[e];
        atomicAdd(&g_acc[1], (double)(lse - lg[rl]));
    }
}

// ---------------- LU: 64x64 diagonal block (1 block) ----------------
__global__ __launch_bounds__(256) void k_ludiag(int kb){
    __shared__ float s[64][65];
    __shared__ double lacc;
    __shared__ int lneg, lbad;
    int tid = threadIdx.x;
    int k0 = kb*64;
#pragma unroll
    for(int l=0;l<16;l++){
        int idx=l*256+tid; int i=idx>>6, j=idx&63;
        s[i][j] = g_M[(size_t)(k0+i)*N + k0+j];
    }
    if(tid==0){ lacc=0.0; lneg=0; lbad=0; }
    __syncthreads();
    for(int j=0;j<64;j++){
        float piv = s[j][j];
        if(tid==0){
            if(!(fabsf(piv) > 0.f) || isinf(piv)) lbad = 1;
            if(piv < 0.f) lneg ^= 1;
            lacc += log(fabs((double)piv));
        }
        float invp = 1.0f/piv;
        if(tid > j && tid < 64) s[tid][j] *= invp;
        __syncthreads();
        int w = 63-j;
        for(int idx=tid; idx < w*w; idx += 256){
            int r  = j+1 + idx / w;
            int cc = j+1 + idx % w;
            s[r][cc] -= s[r][j]*s[j][cc];
        }
        __syncthreads();
    }
#pragma unroll
    for(int l=0;l<16;l++){
        int idx=l*256+tid; int i=idx>>6, j=idx&63;
        g_M[(size_t)(k0+i)*N + k0+j] = s[i][j];
    }
    if(tid==0){
        atomicAdd(&g_acc[2], lacc);
        atomicAdd(&g_neg, lneg);
        if(lbad) atomicAdd(&g_bad, 1);
    }
}

// ---------------- TRSM: L21 = A21 * U11^{-1} (warp per row) ----------------
__global__ __launch_bounds__(256) void k_trsmL(int kb){
    int k0 = kb*64;
    __shared__ float Us[64][65];
    __shared__ float invd[64];
    int tid=threadIdx.x, lane=tid&31, wid=tid>>5;
#pragma unroll
    for(int l=0;l<16;l++){
        int idx=l*256+tid; int i=idx>>6, j=idx&63;
        Us[i][j] = g_M[(size_t)(k0+i)*N + k0+j];
    }
    __syncthreads();
    if(tid<64) invd[tid] = 1.0f/Us[tid][tid];
    __syncthreads();
    int r = k0+64 + blockIdx.x*8 + wid;
    float v0 = g_M[(size_t)r*N + k0 + lane];
    float v1 = g_M[(size_t)r*N + k0 + 32 + lane];
#pragma unroll
    for(int j=0;j<64;j++){
        float aj = (j<32) ? __shfl_sync(0xffffffffu, v0, j)
                          : __shfl_sync(0xffffffffu, v1, j-32);
        float xj = aj * invd[j];
        if(j<32){
            if(lane==j)  v0 = xj;
            if(lane> j)  v0 -= xj*Us[j][lane];
            v1 -= xj*Us[j][32+lane];
        } else {
            int jj = j-32;
            if(lane==jj) v1 = xj;
            if(lane> jj) v1 -= xj*Us[j][32+lane];
        }
    }
    g_M[(size_t)r*N + k0 + lane]      = v0;
    g_M[(size_t)r*N + k0 + 32 + lane] = v1;
}

// ---------------- TRSM: U12 = L11^{-1} * A12 (warp per column) ----------------
__global__ __launch_bounds__(256) void k_trsmU(int kb){
    int k0 = kb*64;
    __shared__ float Ls[64][65];
    int tid=threadIdx.x, lane=tid&31, wid=tid>>5;
#pragma unroll
    for(int l=0;l<16;l++){
        int idx=l*256+tid; int i=idx>>6, j=idx&63;
        Ls[i][j] = g_M[(size_t)(k0+i)*N + k0+j];
    }
    __syncthreads();
    int c = k0+64 + blockIdx.x*8 + wid;
    float v0 = g_M[(size_t)(k0+lane)*N + c];
    float v1 = g_M[(size_t)(k0+32+lane)*N + c];
#pragma unroll
    for(int t=0;t<64;t++){
        float xt = (t<32) ? __shfl_sync(0xffffffffu, v0, t)
                          : __shfl_sync(0xffffffffu, v1, t-32);
        if(t<32){
            if(lane>t) v0 -= Ls[lane][t]*xt;
            v1 -= Ls[32+lane][t]*xt;
        } else {
            int tt = t-32;
            if(lane>tt) v1 -= Ls[32+lane][t]*xt;
        }
    }
    g_M[(size_t)(k0+lane)*N + c]    = v0;
    g_M[(size_t)(k0+32+lane)*N + c] = v1;
}

// ---------------- trailing update: A22 -= L21 @ U12 ----------------
__global__ __launch_bounds__(256) void k_gemmupd(int kb){
    int k0 = kb*64;
    __shared__ float Ls[64][65];   // [t][row]
    __shared__ float Us[64][65];   // [t][col]
    int tid=threadIdx.x, tx=tid&15, ty=tid>>4;
    int r0 = k0+64 + blockIdx.y*64;
    int c0 = k0+64 + blockIdx.x*64;
#pragma unroll
    for(int l=0;l<16;l++){
        int idx=l*256+tid; int i=idx>>6, t=idx&63;
        Ls[t][i] = g_M[(size_t)(r0+i)*N + k0+t];
        Us[i][t] = g_M[(size_t)(k0+i)*N + c0+t];
    }
    __syncthreads();
    float acc[4][4];
#pragma unroll
    for(int i=0;i<4;i++)
#pragma unroll
        for(int j=0;j<4;j++) acc[i][j]=0.f;
#pragma unroll 8
    for(int t=0;t<64;t++){
        float a[4],b[4];
#pragma unroll
        for(int i=0;i<4;i++) a[i]=Ls[t][ty+16*i];
#pragma unroll
        for(int j=0;j<4;j++) b[j]=Us[t][tx+16*j];
#pragma unroll
        for(int i=0;i<4;i++)
#pragma unroll
            for(int j=0;j<4;j++) acc[i][j] += a[i]*b[j];
    }
#pragma unroll
    for(int i=0;i<4;i++)
#pragma unroll
        for(int j=0;j<4;j++){
            size_t off = (size_t)(r0+ty+16*i)*N + (c0+tx+16*j);
            g_M[off] -= acc[i][j];
        }
}

// ---------------- finalize ----------------
__global__ void k_final(const int* __restrict__ troot, float* __restrict__ out){
    int root = troot[0];
    float gold = g_rs[root] + (float)g_acc[0];
    bool pos = ((g_neg & 1)==0) && (g_bad==0);
    float logdet = pos ? (float)g_acc[2] : __int_as_float(0x7fc00000);
    float notnan = (!isnan(gold) && !isnan(logdet)) ? 1.f : 0.f;
    float mask = (gold <= logdet*notnan) ? 1.f : 0.f;
    float loss = (logdet - gold)*mask;
    if(isnan(loss)) loss = 0.f;
    out[0] = 0.25f*loss + (float)g_acc[1];
}

// ---------------- launch ----------------
extern "C" void kernel_launch(void* const* d_in, const int* in_sizes, int n_in,
                              void* d_out, int out_size){
    const float* X     = (const float*)d_in[0];
    const float* Ladj  = (const float*)d_in[1];
    const float* Radj  = (const float*)d_in[2];
    const float* Wb    = (const float*)d_in[3];
    const float* bb    = (const float*)d_in[4];
    const float* Wh    = (const float*)d_in[5];
    const float* Wd    = (const float*)d_in[6];
    const float* Wr1   = (const float*)d_in[7];
    const float* br1   = (const float*)d_in[8];
    const float* Wr2   = (const float*)d_in[9];
    const float* br2   = (const float*)d_in[10];
    const float* Wrel1 = (const float*)d_in[11];
    const float* brel1 = (const float*)d_in[12];
    const float* Wrel2 = (const float*)d_in[13];
    const float* brel2 = (const float*)d_in[14];
    const int*   chl   = (const int*)d_in[15];
    const int*   par   = (const int*)d_in[16];
    const int*   rels  = (const int*)d_in[17];
    const int*   troot = (const int*)d_in[18];

    k_init<<<1,32>>>();
    k_computeU<<<dim3(H/64, N/64, 2), 256>>>(X, Wb);
    k_headdep<<<N, 256>>>(X, Wh, Wd, Wr1, br1, Wr2, br2);
    k_compatA<<<dim3(N/64, N/64), 256>>>(X, bb);
    k_colsum<<<N/256, 256>>>();
    k_buildM<<<dim3(N/256, N), 256>>>();
    k_gold<<<NEDGE, 256>>>(X, Ladj, Radj, bb, par, chl);
    k_ce<<<NEDGE, 256>>>(X, Wrel1, brel1, Wrel2, brel2, par, chl, rels);

    for(int kb=0; kb<NKB; kb++){
        k_ludiag<<<1,256>>>(kb);
        int m = N - 64*(kb+1);
        if(m > 0){
            k_trsmL<<<m/8, 256>>>(kb);
            k_trsmU<<<m/8, 256>>>(kb);
            k_gemmupd<<<dim3(m/64, m/64), 256>>>(kb);
        }
    }
    k_final<<<1,1>>>(troot, (float*)d_out);
}

// round 15
// speedup vs baseline: 1.2517x; 1.2517x over previous
#include <cuda_runtime.h>
#include <math.h>

#define N 3072
#define H 256
#define NEDGE (N-1)
#define NREL 18
#define NB 64
#define NKB (N/NB)   // 48

// ---------------- device scratch (no allocations allowed) ----------------
__device__ float g_U[2*N*H];      // U_k = X @ W_bilin[k]
__device__ float g_hd[2*N];       // head scores per k
__device__ float g_dp[2*N];       // dep scores per k
__device__ float g_rs[N];         // root scores
__device__ float g_A[N*N];        // A = exp(c0)+exp(c1)
__device__ float g_M[N*N];        // permuted Laplacian -> LU in place
__device__ float g_colsum[N];     // off-diagonal column sums of A
__device__ double g_acc[3];       // 0: gold(edges), 1: ce, 2: log|det| sum
__device__ int g_neg;             // negative-pivot parity count
__device__ int g_bad;             // zero/nan/inf pivot flag

__device__ __forceinline__ float gelu_exact(float v){
    return 0.5f * v * (1.0f + erff(v * 0.70710678118654752f));
}

// ---------------- init ----------------
__global__ void k_init(){
    int j = blockIdx.x*256 + threadIdx.x;
    if(j < N) g_colsum[j] = 0.f;
    if(blockIdx.x==0 && threadIdx.x == 0){
        g_acc[0]=0.0; g_acc[1]=0.0; g_acc[2]=0.0;
        g_neg=0; g_bad=0;
    }
}

// ---------------- U_k = X @ W_bilin[k]  (grid: (H/64, N/64, 2)) ----------------
__global__ __launch_bounds__(256) void k_computeU(const float* __restrict__ X,
                                                  const float* __restrict__ Wb){
    int kk = blockIdx.z;
    const float* W = Wb + kk*H*H;
    float* Uo = g_U + kk*N*H;
    __shared__ float As[32][65];   // [h][row]
    __shared__ float Bs[32][65];   // [h][col]
    int tid = threadIdx.x;
    int tx = tid & 15, ty = tid >> 4;
    int r0 = blockIdx.y*64, c0 = blockIdx.x*64;
    float acc[4][4];
#pragma unroll
    for(int i=0;i<4;i++)
#pragma unroll
        for(int j=0;j<4;j++) acc[i][j]=0.f;
    for(int h0=0; h0<H; h0+=32){
#pragma unroll
        for(int l=0;l<8;l++){
            int idx = l*256+tid;
            int i = idx>>5, t = idx&31;
            As[t][i] = X[(r0+i)*H + h0 + t];
        }
#pragma unroll
        for(int l=0;l<8;l++){
            int idx = l*256+tid;
            int t = idx>>6, c = idx&63;
            Bs[t][c] = W[(h0+t)*H + c0 + c];
        }
        __syncthreads();
#pragma unroll 8
        for(int t=0;t<32;t++){
            float a[4], b[4];
#pragma unroll
            for(int i=0;i<4;i++) a[i]=As[t][ty+16*i];
#pragma unroll
            for(int j=0;j<4;j++) b[j]=Bs[t][tx+16*j];
#pragma unroll
            for(int i=0;i<4;i++)
#pragma unroll
                for(int j=0;j<4;j++) acc[i][j] += a[i]*b[j];
        }
        __syncthreads();
    }
#pragma unroll
    for(int i=0;i<4;i++)
#pragma unroll
        for(int j=0;j<4;j++)
            Uo[(r0+ty+16*i)*H + c0+tx+16*j] = acc[i][j];
}

// ---------------- head/dep scores + root scores (grid: N blocks) ----------------
__global__ __launch_bounds__(256) void k_headdep(const float* __restrict__ X,
        const float* __restrict__ Wh, const float* __restrict__ Wd,
        const float* __restrict__ Wr1, const float* __restrict__ br1,
        const float* __restrict__ Wr2, const float* __restrict__ br2){
    int i = blockIdx.x, t = threadIdx.x;
    __shared__ float xs[H];
    __shared__ float red[256];
    xs[t] = X[i*H+t];
    __syncthreads();
    float acc = 0.f;
#pragma unroll 8
    for(int d=0; d<H; d++) acc += xs[d]*Wr1[d*H+t];
    acc += br1[t];
    float g = gelu_exact(acc);
    float vals[5];
    vals[0] = g*Wr2[t];
    vals[1] = xs[t]*Wh[t];
    vals[2] = xs[t]*Wh[H+t];
    vals[3] = xs[t]*Wd[t];
    vals[4] = xs[t]*Wd[H+t];
    float out[5];
#pragma unroll
    for(int v=0; v<5; v++){
        red[t]=vals[v]; __syncthreads();
        for(int s=128;s>0;s>>=1){ if(t<s) red[t]+=red[t+s]; __syncthreads(); }
        out[v]=red[0]; __syncthreads();
    }
    if(t==0){
        g_rs[i]   = out[0] + br2[0];
        g_hd[i]   = out[1];
        g_hd[N+i] = out[2];
        g_dp[i]   = out[3];
        g_dp[N+i] = out[4];
    }
}

// ---------------- A[i][j] = exp(c0)+exp(c1)  (grid: (N/64, N/64)) ----------------
__global__ __launch_bounds__(256) void k_compatA(const float* __restrict__ X,
                                                 const float* __restrict__ bb){
    __shared__ float U0s[32][65], U1s[32][65], Xs[32][65];
    int tid=threadIdx.x, tx=tid&15, ty=tid>>4;
    int r0=blockIdx.y*64, c0=blockIdx.x*64;
    float a0[4][4], a1[4][4];
#pragma unroll
    for(int i=0;i<4;i++)
#pragma unroll
        for(int j=0;j<4;j++){ a0[i][j]=0.f; a1[i][j]=0.f; }
    const float* U0 = g_U;
    const float* U1 = g_U + N*H;
    for(int d0=0; d0<H; d0+=32){
#pragma unroll
        for(int l=0;l<8;l++){
            int idx=l*256+tid; int i=idx>>5, t=idx&31;
            U0s[t][i] = U0[(r0+i)*H + d0+t];
            U1s[t][i] = U1[(r0+i)*H + d0+t];
            Xs[t][i]  = X [(c0+i)*H + d0+t];
        }
        __syncthreads();
#pragma unroll 8
        for(int t=0;t<32;t++){
            float x0[4],x1[4],b[4];
#pragma unroll
            for(int i=0;i<4;i++){ x0[i]=U0s[t][ty+16*i]; x1[i]=U1s[t][ty+16*i]; }
#pragma unroll
            for(int j=0;j<4;j++) b[j]=Xs[t][tx+16*j];
#pragma unroll
            for(int i=0;i<4;i++)
#pragma unroll
                for(int j=0;j<4;j++){ a0[i][j]+=x0[i]*b[j]; a1[i][j]+=x1[i]*b[j]; }
        }
        __syncthreads();
    }
    float bb0=bb[0], bb1=bb[1];
#pragma unroll
    for(int i=0;i<4;i++){
        int r = r0+ty+16*i;
        float h0=g_hd[r], h1=g_hd[N+r];
#pragma unroll
        for(int j=0;j<4;j++){
            int c = c0+tx+16*j;
            float c0v = a0[i][j] + bb0 + h0 + g_dp[c];
            float c1v = a1[i][j] + bb1 + h1 + g_dp[N+c];
            g_A[r*N+c] = expf(c0v) + expf(c1v);
        }
    }
}

// ---------------- off-diagonal column sums (grid: (N/256, 8)) ----------------
__global__ void k_colsum(){
    int j = blockIdx.x*256 + threadIdx.x;
    int i0 = blockIdx.y * (N/8);
    float s = 0.f;
    for(int i=i0; i<i0+(N/8); i++){
        if(i!=j) s += g_A[(size_t)i*N+j];
    }
    atomicAdd(&g_colsum[j], s);
}

// ---------------- build permuted Laplacian M (grid: (N/256, N)) ----------------
__global__ void k_buildM(){
    int j = blockIdx.x*256 + threadIdx.x;
    int i = blockIdx.y;
    int oi = (i==N-1) ? 0 : (i+1);
    int oj = (j==N-1) ? 0 : (j+1);
    float v;
    if(oi==0)          v = expf(g_rs[oj]);     // replaced row
    else if(oi==oj)    v = g_colsum[oj];       // exact off-diag column sum
    else               v = -g_A[(size_t)oi*N+oj];
    g_M[(size_t)i*N+j] = v;
}

// ---------------- gold: gather compat at edges ----------------
__global__ __launch_bounds__(256) void k_gold(const float* __restrict__ X,
        const float* __restrict__ Ladj, const float* __restrict__ Radj,
        const float* __restrict__ bb,
        const int* __restrict__ par, const int* __restrict__ chl){
    int e = blockIdx.x, t = threadIdx.x;
    int p = par[e], c = chl[e];
    __shared__ float red[256];
    float xc = X[c*H+t];
    float s0 = g_U[p*H+t]*xc;
    float s1 = g_U[N*H + p*H+t]*xc;
    red[t]=s0; __syncthreads();
    for(int s=128;s>0;s>>=1){ if(t<s) red[t]+=red[t+s]; __syncthreads(); }
    float r0v = red[0]; __syncthreads();
    red[t]=s1; __syncthreads();
    for(int s=128;s>0;s>>=1){ if(t<s) red[t]+=red[t+s]; __syncthreads(); }
    float r1v = red[0];
    if(t==0){
        float c0v = r0v + bb[0] + g_hd[p]   + g_dp[c];
        float c1v = r1v + bb[1] + g_hd[N+p] + g_dp[N+c];
        float lf = Ladj[(size_t)p*N+c];
        float rf = Radj[(size_t)p*N+c];
        atomicAdd(&g_acc[0], (double)(lf*c0v + rf*c1v));
    }
}

// ---------------- relation CE loss ----------------
__global__ __launch_bounds__(256) void k_ce(const float* __restrict__ X,
        const float* __restrict__ Wrel1, const float* __restrict__ brel1,
        const float* __restrict__ Wrel2, const float* __restrict__ brel2,
        const int* __restrict__ par, const int* __restrict__ chl,
        const int* __restrict__ rels){
    int e = blockIdx.x, t = threadIdx.x;
    int p = par[e], c = chl[e];
    __shared__ float xp[H], xc[H], hs[H];
    __shared__ float lg[NREL];
    xp[t] = X[p*H+t];
    xc[t] = X[c*H+t];
    __syncthreads();
    float acc = brel1[t];
#pragma unroll 8
    for(int d=0; d<H; d++) acc += xp[d]*Wrel1[d*H + t];
#pragma unroll 8
    for(int d=0; d<H; d++) acc += xc[d]*Wrel1[(H+d)*H + t];
    hs[t] = gelu_exact(acc);
    __syncthreads();
    if(t < NREL){
        float a = brel2[t];
        for(int u=0; u<H; u++) a += hs[u]*Wrel2[u*NREL + t];
        lg[t] = a;
    }
    __syncthreads();
    if(t==0){
        float mx = lg[0];
#pragma unroll
        for(int r=1;r<NREL;r++) mx = fmaxf(mx, lg[r]);
        float s = 0.f;
#pragma unroll
        for(int r=0;r<NREL;r++) s += expf(lg[r]-mx);
        float lse = mx + logf(s);
        int rl = rels[e];
        atomicAdd(&g_acc[1], (double)(lse - lg[rl]));
    }
}

// ---------------- LU: 64x64 diagonal block, register-resident ----------------
// thread tid: row r = tid>>2, column slice cq = tid&3 (cols cq*16..cq*16+15)
__global__ __launch_bounds__(256) void k_ludiag(int kb){
    int k0 = kb*64;
    int tid = threadIdx.x;
    int r = tid>>2, cq = tid&3;
    __shared__ float rowbuf[64];
    __shared__ float pivbuf[64];
    __shared__ int sneg, sbad;
    float v[16];
    const float4* gp = (const float4*)(g_M + (size_t)(k0+r)*N + k0);
    float4 a0 = gp[cq*4+0], a1 = gp[cq*4+1], a2 = gp[cq*4+2], a3 = gp[cq*4+3];
    v[0]=a0.x; v[1]=a0.y; v[2]=a0.z; v[3]=a0.w;
    v[4]=a1.x; v[5]=a1.y; v[6]=a1.z; v[7]=a1.w;
    v[8]=a2.x; v[9]=a2.y; v[10]=a2.z; v[11]=a2.w;
    v[12]=a3.x; v[13]=a3.y; v[14]=a3.z; v[15]=a3.w;
    if(tid==0){ sneg=0; sbad=0; }
#pragma unroll
    for(int j=0;j<64;j++){
        if(r==j){
#pragma unroll
            for(int ci=0;ci<16;ci++) rowbuf[(cq<<4)+ci] = v[ci];
        }
        __syncthreads();
        float piv = rowbuf[j];
        if(tid==0) pivbuf[j] = piv;
        float invp = 1.0f/piv;
        float l = __shfl_sync(0xffffffffu, v[j&15], ((r&7)<<2)|(j>>4)) * invp;
        if(r>j){
            if(cq == (j>>4)) v[j&15] = l;
#pragma unroll
            for(int ci=0;ci<16;ci++){
                int c = (cq<<4)+ci;
                if(c>j) v[ci] -= l*rowbuf[c];
            }
        }
        __syncthreads();
    }
    // write back
    float4 o;
    float4* op = (float4*)(g_M + (size_t)(k0+r)*N + k0);
    o.x=v[0]; o.y=v[1]; o.z=v[2]; o.w=v[3];  op[cq*4+0]=o;
    o.x=v[4]; o.y=v[5]; o.z=v[6]; o.w=v[7];  op[cq*4+1]=o;
    o.x=v[8]; o.y=v[9]; o.z=v[10]; o.w=v[11]; op[cq*4+2]=o;
    o.x=v[12]; o.y=v[13]; o.z=v[14]; o.w=v[15]; op[cq*4+3]=o;
    // pivot bookkeeping
    if(tid < 64){
        float p = pivbuf[tid];
        if(!(fabsf(p) > 0.f) || isinf(p)) atomicOr(&sbad, 1);
        if(p < 0.f) atomicXor(&sneg, 1);
    }
    __syncthreads();
    if(tid==0){
        double lacc = 0.0;
        for(int j=0;j<64;j++) lacc += log(fabs((double)pivbuf[j]));
        atomicAdd(&g_acc[2], lacc);
        atomicAdd(&g_neg, sneg);
        if(sbad) atomicAdd(&g_bad, 1);
    }
}

// ---------------- fused TRSM: y==0 -> L21 tiles, y==1 -> U12 tiles ----------------
__global__ __launch_bounds__(256) void k_trsm(int kb){
    int k0 = kb*64;
    int tid = threadIdx.x;
    int off = k0 + 64 + blockIdx.x*64;
    __shared__ float D[64][65];
    __shared__ float S[64][65];
    __shared__ float invd[64];
#pragma unroll
    for(int l=0;l<16;l++){
        int idx=l*256+tid; int i=idx>>6, j=idx&63;
        D[i][j] = g_M[(size_t)(k0+i)*N + k0+j];
    }
    __syncthreads();   // D fully resident before ANY use (invd read below crosses threads)
    if(blockIdx.y==0){
        // Solve X * U11 = A21 for 64 rows starting at 'off'.
        if(tid<64) invd[tid] = 1.0f/D[tid][tid];
        __syncthreads();
        int r = tid>>2, cq = tid&3;
        float v[16];
        const float4* gp = (const float4*)(g_M + (size_t)(off+r)*N + k0);
        float4 a0=gp[cq*4+0], a1=gp[cq*4+1], a2=gp[cq*4+2], a3=gp[cq*4+3];
        v[0]=a0.x; v[1]=a0.y; v[2]=a0.z; v[3]=a0.w;
        v[4]=a1.x; v[5]=a1.y; v[6]=a1.z; v[7]=a1.w;
        v[8]=a2.x; v[9]=a2.y; v[10]=a2.z; v[11]=a2.w;
        v[12]=a3.x; v[13]=a3.y; v[14]=a3.z; v[15]=a3.w;
#pragma unroll
        for(int j=0;j<64;j++){
            float xj = __shfl_sync(0xffffffffu, v[j&15], ((r&7)<<2)|(j>>4));
            xj *= invd[j];
            if(cq == (j>>4)) v[j&15] = xj;
#pragma unroll
            for(int ci=0;ci<16;ci++){
                int c = (cq<<4)+ci;
                if(c>j) v[ci] -= xj*D[j][c];
            }
        }
        float4 o;
        float4* op = (float4*)(g_M + (size_t)(off+r)*N + k0);
        o.x=v[0]; o.y=v[1]; o.z=v[2]; o.w=v[3];   op[cq*4+0]=o;
        o.x=v[4]; o.y=v[5]; o.z=v[6]; o.w=v[7];   op[cq*4+1]=o;
        o.x=v[8]; o.y=v[9]; o.z=v[10]; o.w=v[11]; op[cq*4+2]=o;
        o.x=v[12]; o.y=v[13]; o.z=v[14]; o.w=v[15]; op[cq*4+3]=o;
    } else {
        // Solve L11 * X = A12 for 64 columns starting at 'off'.
#pragma unroll
        for(int l=0;l<16;l++){
            int idx=l*256+tid; int i=idx>>6, j=idx&63;
            S[i][j] = g_M[(size_t)(k0+i)*N + off+j];
        }
        __syncthreads();
        int c = tid>>2, rq = tid&3;
        float v[16];
#pragma unroll
        for(int ri=0;ri<16;ri++) v[ri] = S[(rq<<4)+ri][c];
        __syncthreads();
#pragma unroll
        for(int t=0;t<64;t++){
            float xt = __shfl_sync(0xffffffffu, v[t&15], ((c&7)<<2)|(t>>4));
#pragma unroll
            for(int ri=0;ri<16;ri++){
                int rr = (rq<<4)+ri;
                if(rr>t) v[ri] -= D[rr][t]*xt;
            }
        }
#pragma unroll
        for(int ri=0;ri<16;ri++) S[(rq<<4)+ri][c] = v[ri];
        __syncthreads();
#pragma unroll
        for(int l=0;l<16;l++){
            int idx=l*256+tid; int i=idx>>6, j=idx&63;
            g_M[(size_t)(k0+i)*N + off+j] = S[i][j];
        }
    }
}

// ---------------- trailing update: A22 -= L21 @ U12 ----------------
__global__ __launch_bounds__(256) void k_gemmupd(int kb){
    int k0 = kb*64;
    __shared__ float Ls[64][65];   // [t][row]
    __shared__ float Us[64][65];   // [t][col]
    int tid=threadIdx.x, tx=tid&15, ty=tid>>4;
    int r0 = k0+64 + blockIdx.y*64;
    int c0 = k0+64 + blockIdx.x*64;
#pragma unroll
    for(int l=0;l<16;l++){
        int idx=l*256+tid; int i=idx>>6, t=idx&63;
        Ls[t][i] = g_M[(size_t)(r0+i)*N + k0+t];
        Us[i][t] = g_M[(size_t)(k0+i)*N + c0+t];
    }
    __syncthreads();
    float acc[4][4];
#pragma unroll
    for(int i=0;i<4;i++)
#pragma unroll
        for(int j=0;j<4;j++) acc[i][j]=0.f;
#pragma unroll 8
    for(int t=0;t<64;t++){
        float a[4],b[4];
#pragma unroll
        for(int i=0;i<4;i++) a[i]=Ls[t][ty+16*i];
#pragma unroll
        for(int j=0;j<4;j++) b[j]=Us[t][tx+16*j];
#pragma unroll
        for(int i=0;i<4;i++)
#pragma unroll
            for(int j=0;j<4;j++) acc[i][j] += a[i]*b[j];
    }
#pragma unroll
    for(int i=0;i<4;i++)
#pragma unroll
        for(int j=0;j<4;j++){
            size_t offm = (size_t)(r0+ty+16*i)*N + (c0+tx+16*j);
            g_M[offm] -= acc[i][j];
        }
}

// ---------------- finalize ----------------
__global__ void k_final(const int* __restrict__ troot, float* __restrict__ out){
    int root = troot[0];
    float gold = g_rs[root] + (float)g_acc[0];
    bool pos = ((g_neg & 1)==0) && (g_bad==0);
    float logdet = pos ? (float)g_acc[2] : __int_as_float(0x7fc00000);
    float notnan = (!isnan(gold) && !isnan(logdet)) ? 1.f : 0.f;
    float mask = (gold <= logdet*notnan) ? 1.f : 0.f;
    float loss = (logdet - gold)*mask;
    if(isnan(loss)) loss = 0.f;
    out[0] = 0.25f*loss + (float)g_acc[1];
}

// ---------------- launch ----------------
extern "C" void kernel_launch(void* const* d_in, const int* in_sizes, int n_in,
                              void* d_out, int out_size){
    const float* X     = (const float*)d_in[0];
    const float* Ladj  = (const float*)d_in[1];
    const float* Radj  = (const float*)d_in[2];
    const float* Wb    = (const float*)d_in[3];
    const float* bb    = (const float*)d_in[4];
    const float* Wh    = (const float*)d_in[5];
    const float* Wd    = (const float*)d_in[6];
    const float* Wr1   = (const float*)d_in[7];
    const float* br1   = (const float*)d_in[8];
    const float* Wr2   = (const float*)d_in[9];
    const float* br2   = (const float*)d_in[10];
    const float* Wrel1 = (const float*)d_in[11];
    const float* brel1 = (const float*)d_in[12];
    const float* Wrel2 = (const float*)d_in[13];
    const float* brel2 = (const float*)d_in[14];
    const int*   chl   = (const int*)d_in[15];
    const int*   par   = (const int*)d_in[16];
    const int*   rels  = (const int*)d_in[17];
    const int*   troot = (const int*)d_in[18];

    k_init<<<N/256, 256>>>();
    k_computeU<<<dim3(H/64, N/64, 2), 256>>>(X, Wb);
    k_headdep<<<N, 256>>>(X, Wh, Wd, Wr1, br1, Wr2, br2);
    k_compatA<<<dim3(N/64, N/64), 256>>>(X, bb);
    k_colsum<<<dim3(N/256, 8), 256>>>();
    k_buildM<<<dim3(N/256, N), 256>>>();
    k_gold<<<NEDGE, 256>>>(X, Ladj, Radj, bb, par, chl);
    k_ce<<<NEDGE, 256>>>(X, Wrel1, brel1, Wrel2, brel2, par, chl, rels);

    for(int kb=0; kb<NKB; kb++){
        k_ludiag<<<1,256>>>(kb);
        int m = N - 64*(kb+1);
        if(m > 0){
            k_trsm<<<dim3(m/64, 2), 256>>>(kb);
            k_gemmupd<<<dim3(m/64, m/64), 256>>>(kb);
        }
    }
    k_final<<<1,1>>>(troot, (float*)d_out);
}

// round 16
// speedup vs baseline: 1.2884x; 1.0294x over previous
#include <cuda_runtime.h>
#include <math.h>

#define N 3072
#define H 256
#define NEDGE (N-1)
#define NREL 18
#define NB 64
#define NKB (N/NB)   // 48
#define GRID_LU 444  // 3 blocks/SM * 148 SMs, co-residency forced by __launch_bounds__(256,3)

// ---------------- device scratch (no allocations allowed) ----------------
__device__ float g_U[2*N*H];      // U_k = X @ W_bilin[k]
__device__ float g_hd[2*N];       // head scores per k
__device__ float g_dp[2*N];       // dep scores per k
__device__ float g_rs[N];         // root scores
__device__ float g_A[N*N];        // A = exp(c0)+exp(c1)
__device__ float g_M[N*N];        // permuted Laplacian -> LU in place
__device__ float g_colsum[N];     // off-diagonal column sums of A
__device__ double g_acc[3];       // 0: gold(edges), 1: ce, 2: log|det| sum
__device__ int g_neg;             // negative-pivot parity count
__device__ int g_bad;             // zero/nan/inf pivot flag
__device__ unsigned g_sync_cnt;
__device__ unsigned g_sync_gen;

__device__ __forceinline__ float gelu_exact(float v){
    return 0.5f * v * (1.0f + erff(v * 0.70710678118654752f));
}

// ---------------- init ----------------
__global__ void k_init(){
    int j = blockIdx.x*256 + threadIdx.x;
    if(j < N) g_colsum[j] = 0.f;
    if(blockIdx.x==0 && threadIdx.x == 0){
        g_acc[0]=0.0; g_acc[1]=0.0; g_acc[2]=0.0;
        g_neg=0; g_bad=0;
        g_sync_cnt=0u; g_sync_gen=0u;
    }
}

// ---------------- U_k = X @ W_bilin[k]  (grid: (H/64, N/64, 2)) ----------------
__global__ __launch_bounds__(256) void k_computeU(const float* __restrict__ X,
                                                  const float* __restrict__ Wb){
    int kk = blockIdx.z;
    const float* W = Wb + kk*H*H;
    float* Uo = g_U + kk*N*H;
    __shared__ float As[32][65];
    __shared__ float Bs[32][65];
    int tid = threadIdx.x;
    int tx = tid & 15, ty = tid >> 4;
    int r0 = blockIdx.y*64, c0 = blockIdx.x*64;
    float acc[4][4];
#pragma unroll
    for(int i=0;i<4;i++)
#pragma unroll
        for(int j=0;j<4;j++) acc[i][j]=0.f;
    for(int h0=0; h0<H; h0+=32){
#pragma unroll
        for(int l=0;l<8;l++){
            int idx = l*256+tid;
            int i = idx>>5, t = idx&31;
            As[t][i] = X[(r0+i)*H + h0 + t];
        }
#pragma unroll
        for(int l=0;l<8;l++){
            int idx = l*256+tid;
            int t = idx>>6, c = idx&63;
            Bs[t][c] = W[(h0+t)*H + c0 + c];
        }
        __syncthreads();
#pragma unroll 8
        for(int t=0;t<32;t++){
            float a[4], b[4];
#pragma unroll
            for(int i=0;i<4;i++) a[i]=As[t][ty+16*i];
#pragma unroll
            for(int j=0;j<4;j++) b[j]=Bs[t][tx+16*j];
#pragma unroll
            for(int i=0;i<4;i++)
#pragma unroll
                for(int j=0;j<4;j++) acc[i][j] += a[i]*b[j];
        }
        __syncthreads();
    }
#pragma unroll
    for(int i=0;i<4;i++)
#pragma unroll
        for(int j=0;j<4;j++)
            Uo[(r0+ty+16*i)*H + c0+tx+16*j] = acc[i][j];
}

// ---------------- head/dep scores + root scores (grid: N blocks) ----------------
__global__ __launch_bounds__(256) void k_headdep(const float* __restrict__ X,
        const float* __restrict__ Wh, const float* __restrict__ Wd,
        const float* __restrict__ Wr1, const float* __restrict__ br1,
        const float* __restrict__ Wr2, const float* __restrict__ br2){
    int i = blockIdx.x, t = threadIdx.x;
    __shared__ float xs[H];
    __shared__ float red[256];
    xs[t] = X[i*H+t];
    __syncthreads();
    float acc = 0.f;
#pragma unroll 8
    for(int d=0; d<H; d++) acc += xs[d]*Wr1[d*H+t];
    acc += br1[t];
    float g = gelu_exact(acc);
    float vals[5];
    vals[0] = g*Wr2[t];
    vals[1] = xs[t]*Wh[t];
    vals[2] = xs[t]*Wh[H+t];
    vals[3] = xs[t]*Wd[t];
    vals[4] = xs[t]*Wd[H+t];
    float out[5];
#pragma unroll
    for(int v=0; v<5; v++){
        red[t]=vals[v]; __syncthreads();
        for(int s=128;s>0;s>>=1){ if(t<s) red[t]+=red[t+s]; __syncthreads(); }
        out[v]=red[0]; __syncthreads();
    }
    if(t==0){
        g_rs[i]   = out[0] + br2[0];
        g_hd[i]   = out[1];
        g_hd[N+i] = out[2];
        g_dp[i]   = out[3];
        g_dp[N+i] = out[4];
    }
}

// ---------------- A[i][j] = exp(c0)+exp(c1)  (grid: (N/64, N/64)) ----------------
__global__ __launch_bounds__(256) void k_compatA(const float* __restrict__ X,
                                                 const float* __restrict__ bb){
    __shared__ float U0s[32][65], U1s[32][65], Xs[32][65];
    int tid=threadIdx.x, tx=tid&15, ty=tid>>4;
    int r0=blockIdx.y*64, c0=blockIdx.x*64;
    float a0[4][4], a1[4][4];
#pragma unroll
    for(int i=0;i<4;i++)
#pragma unroll
        for(int j=0;j<4;j++){ a0[i][j]=0.f; a1[i][j]=0.f; }
    const float* U0 = g_U;
    const float* U1 = g_U + N*H;
    for(int d0=0; d0<H; d0+=32){
#pragma unroll
        for(int l=0;l<8;l++){
            int idx=l*256+tid; int i=idx>>5, t=idx&31;
            U0s[t][i] = U0[(r0+i)*H + d0+t];
            U1s[t][i] = U1[(r0+i)*H + d0+t];
            Xs[t][i]  = X [(c0+i)*H + d0+t];
        }
        __syncthreads();
#pragma unroll 8
        for(int t=0;t<32;t++){
            float x0[4],x1[4],b[4];
#pragma unroll
            for(int i=0;i<4;i++){ x0[i]=U0s[t][ty+16*i]; x1[i]=U1s[t][ty+16*i]; }
#pragma unroll
            for(int j=0;j<4;j++) b[j]=Xs[t][tx+16*j];
#pragma unroll
            for(int i=0;i<4;i++)
#pragma unroll
                for(int j=0;j<4;j++){ a0[i][j]+=x0[i]*b[j]; a1[i][j]+=x1[i]*b[j]; }
        }
        __syncthreads();
    }
    float bb0=bb[0], bb1=bb[1];
#pragma unroll
    for(int i=0;i<4;i++){
        int r = r0+ty+16*i;
        float h0=g_hd[r], h1=g_hd[N+r];
#pragma unroll
        for(int j=0;j<4;j++){
            int c = c0+tx+16*j;
            float c0v = a0[i][j] + bb0 + h0 + g_dp[c];
            float c1v = a1[i][j] + bb1 + h1 + g_dp[N+c];
            g_A[r*N+c] = expf(c0v) + expf(c1v);
        }
    }
}

// ---------------- off-diagonal column sums (grid: (N/256, 8)) ----------------
__global__ void k_colsum(){
    int j = blockIdx.x*256 + threadIdx.x;
    int i0 = blockIdx.y * (N/8);
    float s = 0.f;
    for(int i=i0; i<i0+(N/8); i++){
        if(i!=j) s += g_A[(size_t)i*N+j];
    }
    atomicAdd(&g_colsum[j], s);
}

// ---------------- build permuted Laplacian M (grid: (N/256, N)) ----------------
__global__ void k_buildM(){
    int j = blockIdx.x*256 + threadIdx.x;
    int i = blockIdx.y;
    int oi = (i==N-1) ? 0 : (i+1);
    int oj = (j==N-1) ? 0 : (j+1);
    float v;
    if(oi==0)          v = expf(g_rs[oj]);
    else if(oi==oj)    v = g_colsum[oj];
    else               v = -g_A[(size_t)oi*N+oj];
    g_M[(size_t)i*N+j] = v;
}

// ---------------- gold: gather compat at edges ----------------
__global__ __launch_bounds__(256) void k_gold(const float* __restrict__ X,
        const float* __restrict__ Ladj, const float* __restrict__ Radj,
        const float* __restrict__ bb,
        const int* __restrict__ par, const int* __restrict__ chl){
    int e = blockIdx.x, t = threadIdx.x;
    int p = par[e], c = chl[e];
    __shared__ float red[256];
    float xc = X[c*H+t];
    float s0 = g_U[p*H+t]*xc;
    float s1 = g_U[N*H + p*H+t]*xc;
    red[t]=s0; __syncthreads();
    for(int s=128;s>0;s>>=1){ if(t<s) red[t]+=red[t+s]; __syncthreads(); }
    float r0v = red[0]; __syncthreads();
    red[t]=s1; __syncthreads();
    for(int s=128;s>0;s>>=1){ if(t<s) red[t]+=red[t+s]; __syncthreads(); }
    float r1v = red[0];
    if(t==0){
        float c0v = r0v + bb[0] + g_hd[p]   + g_dp[c];
        float c1v = r1v + bb[1] + g_hd[N+p] + g_dp[N+c];
        float lf = Ladj[(size_t)p*N+c];
        float rf = Radj[(size_t)p*N+c];
        atomicAdd(&g_acc[0], (double)(lf*c0v + rf*c1v));
    }
}

// ---------------- relation CE loss ----------------
__global__ __launch_bounds__(256) void k_ce(const float* __restrict__ X,
        const float* __restrict__ Wrel1, const float* __restrict__ brel1,
        const float* __restrict__ Wrel2, const float* __restrict__ brel2,
        const int* __restrict__ par, const int* __restrict__ chl,
        const int* __restrict__ rels){
    int e = blockIdx.x, t = threadIdx.x;
    int p = par[e], c = chl[e];
    __shared__ float xp[H], xc[H], hs[H];
    __shared__ float lg[NREL];
    xp[t] = X[p*H+t];
    xc[t] = X[c*H+t];
    __syncthreads();
    float acc = brel1[t];
#pragma unroll 8
    for(int d=0; d<H; d++) acc += xp[d]*Wrel1[d*H + t];
#pragma unroll 8
    for(int d=0; d<H; d++) acc += xc[d]*Wrel1[(H+d)*H + t];
    hs[t] = gelu_exact(acc);
    __syncthreads();
    if(t < NREL){
        float a = brel2[t];
        for(int u=0; u<H; u++) a += hs[u]*Wrel2[u*NREL + t];
        lg[t] = a;
    }
    __syncthreads();
    if(t==0){
        float mx = lg[0];
#pragma unroll
        for(int r=1;r<NREL;r++) mx = fmaxf(mx, lg[r]);
        float s = 0.f;
#pragma unroll
        for(int r=0;r<NREL;r++) s += expf(lg[r]-mx);
        float lse = mx + logf(s);
        int rl = rels[e];
        atomicAdd(&g_acc[1], (double)(lse - lg[rl]));
    }
}

// ================= persistent LU =================

__device__ __forceinline__ void gbar(){
    __syncthreads();
    if(threadIdx.x==0){
        __threadfence();
        volatile unsigned* genp = (volatile unsigned*)&g_sync_gen;
        unsigned gen = *genp;
        unsigned arrived = atomicAdd(&g_sync_cnt, 1u);
        if(arrived == GRID_LU-1u){
            g_sync_cnt = 0u;
            __threadfence();
            *genp = gen + 1u;
        } else {
            while(*genp == gen) __nanosleep(64);
            __threadfence();
        }
    }
    __syncthreads();
}

// 64x64 diagonal LU, register-resident; called by block 0 only (all 256 threads)
__device__ void d_ludiag(int kb, float* rowbuf, float* pivbuf){
    int k0 = kb*64;
    int tid = threadIdx.x;
    int r = tid>>2, cq = tid&3;
    float v[16];
    __syncthreads();
    const float4* gp = (const float4*)(g_M + (size_t)(k0+r)*N + k0);
    float4 a0 = gp[cq*4+0], a1 = gp[cq*4+1], a2 = gp[cq*4+2], a3 = gp[cq*4+3];
    v[0]=a0.x; v[1]=a0.y; v[2]=a0.z; v[3]=a0.w;
    v[4]=a1.x; v[5]=a1.y; v[6]=a1.z; v[7]=a1.w;
    v[8]=a2.x; v[9]=a2.y; v[10]=a2.z; v[11]=a2.w;
    v[12]=a3.x; v[13]=a3.y; v[14]=a3.z; v[15]=a3.w;
    __syncthreads();
#pragma unroll
    for(int j=0;j<64;j++){
        if(r==j){
#pragma unroll
            for(int ci=0;ci<16;ci++) rowbuf[(cq<<4)+ci] = v[ci];
        }
        __syncthreads();
        float piv = rowbuf[j];
        if(tid==0) pivbuf[j] = piv;
        float invp = 1.0f/piv;
        float l = __shfl_sync(0xffffffffu, v[j&15], ((r&7)<<2)|(j>>4)) * invp;
        if(r>j){
            if(cq == (j>>4)) v[j&15] = l;
#pragma unroll
            for(int ci=0;ci<16;ci++){
                int c = (cq<<4)+ci;
                if(c>j) v[ci] -= l*rowbuf[c];
            }
        }
        __syncthreads();
    }
    float4 o;
    float4* op = (float4*)(g_M + (size_t)(k0+r)*N + k0);
    o.x=v[0]; o.y=v[1]; o.z=v[2]; o.w=v[3];   op[cq*4+0]=o;
    o.x=v[4]; o.y=v[5]; o.z=v[6]; o.w=v[7];   op[cq*4+1]=o;
    o.x=v[8]; o.y=v[9]; o.z=v[10]; o.w=v[11]; op[cq*4+2]=o;
    o.x=v[12]; o.y=v[13]; o.z=v[14]; o.w=v[15]; op[cq*4+3]=o;
    __syncthreads();
    if(tid==0){
        double lacc = 0.0; int neg=0, bad=0;
        for(int j=0;j<64;j++){
            float p = pivbuf[j];
            if(!(fabsf(p) > 0.f) || isinf(p)) bad = 1;
            if(p < 0.f) neg ^= 1;
            lacc += log(fabs((double)p));
        }
        g_acc[2] += lacc;
        g_neg += neg;
        if(bad) g_bad = 1;
    }
    __syncthreads();
}

// load diagonal tile D + reciprocals (block-cooperative)
__device__ void d_loadD(int kb, float (*D)[65], float* invd){
    int tid = threadIdx.x, k0 = kb*64;
    __syncthreads();
#pragma unroll
    for(int l=0;l<16;l++){
        int idx=l*256+tid; int i=idx>>6, j=idx&63;
        D[i][j] = g_M[(size_t)(k0+i)*N + k0+j];
    }
    __syncthreads();
    if(tid<64) invd[tid] = 1.0f/D[tid][tid];
    __syncthreads();
}

// L21 tile: solve X * U11 = A21 for 64 rows at row0 (register-resident)
__device__ void d_trsmL(int kb, int tile, const float (*D)[65], const float* invd){
    int k0 = kb*64, row0 = tile*64;
    int tid = threadIdx.x;
    int r = tid>>2, cq = tid&3;
    float v[16];
    const float4* gp = (const float4*)(g_M + (size_t)(row0+r)*N + k0);
    float4 a0=gp[cq*4+0], a1=gp[cq*4+1], a2=gp[cq*4+2], a3=gp[cq*4+3];
    v[0]=a0.x; v[1]=a0.y; v[2]=a0.z; v[3]=a0.w;
    v[4]=a1.x; v[5]=a1.y; v[6]=a1.z; v[7]=a1.w;
    v[8]=a2.x; v[9]=a2.y; v[10]=a2.z; v[11]=a2.w;
    v[12]=a3.x; v[13]=a3.y; v[14]=a3.z; v[15]=a3.w;
#pragma unroll
    for(int j=0;j<64;j++){
        float xj = __shfl_sync(0xffffffffu, v[j&15], ((r&7)<<2)|(j>>4));
        xj *= invd[j];
        if(cq == (j>>4)) v[j&15] = xj;
#pragma unroll
        for(int ci=0;ci<16;ci++){
            int c = (cq<<4)+ci;
            if(c>j) v[ci] -= xj*D[j][c];
        }
    }
    float4 o;
    float4* op = (float4*)(g_M + (size_t)(row0+r)*N + k0);
    o.x=v[0]; o.y=v[1]; o.z=v[2]; o.w=v[3];   op[cq*4+0]=o;
    o.x=v[4]; o.y=v[5]; o.z=v[6]; o.w=v[7];   op[cq*4+1]=o;
    o.x=v[8]; o.y=v[9]; o.z=v[10]; o.w=v[11]; op[cq*4+2]=o;
    o.x=v[12]; o.y=v[13]; o.z=v[14]; o.w=v[15]; op[cq*4+3]=o;
}

// U12 tile: solve L11 * X = A12 for 64 cols at col0; stages through S (sB)
__device__ void d_trsmU(int kb, int tile, const float (*D)[65], float (*S)[65]){
    int k0 = kb*64, col0 = tile*64;
    int tid = threadIdx.x;
    __syncthreads();
#pragma unroll
    for(int l=0;l<16;l++){
        int idx=l*256+tid; int i=idx>>6, j=idx&63;
        S[i][j] = g_M[(size_t)(k0+i)*N + col0+j];
    }
    __syncthreads();
    int c = tid>>2, rq = tid&3;
    float v[16];
#pragma unroll
    for(int ri=0;ri<16;ri++) v[ri] = S[(rq<<4)+ri][c];
    __syncthreads();
#pragma unroll
    for(int t=0;t<64;t++){
        float xt = __shfl_sync(0xffffffffu, v[t&15], ((c&7)<<2)|(t>>4));
#pragma unroll
        for(int ri=0;ri<16;ri++){
            int rr = (rq<<4)+ri;
            if(rr>t) v[ri] -= D[rr][t]*xt;
        }
    }
#pragma unroll
    for(int ri=0;ri<16;ri++) S[(rq<<4)+ri][c] = v[ri];
    __syncthreads();
#pragma unroll
    for(int l=0;l<16;l++){
        int idx=l*256+tid; int i=idx>>6, j=idx&63;
        g_M[(size_t)(k0+i)*N + col0+j] = S[i][j];
    }
    __syncthreads();
}

// trailing tile: C(ti,tj) -= L(ti,kb) @ U(kb,tj)
__device__ void d_gemm(int kb, int ti, int tj, float (*Ls)[65], float (*Us)[65]){
    int k0 = kb*64, r0 = ti*64, c0 = tj*64;
    int tid = threadIdx.x, tx = tid&15, ty = tid>>4;
    __syncthreads();
#pragma unroll
    for(int l=0;l<16;l++){
        int idx=l*256+tid; int i=idx>>6, t=idx&63;
        Ls[t][i] = g_M[(size_t)(r0+i)*N + k0+t];
        Us[i][t] = g_M[(size_t)(k0+i)*N + c0+t];
    }
    __syncthreads();
    float acc[4][4];
#pragma unroll
    for(int i=0;i<4;i++)
#pragma unroll
        for(int j=0;j<4;j++) acc[i][j]=0.f;
#pragma unroll 8
    for(int t=0;t<64;t++){
        float a[4],b[4];
#pragma unroll
        for(int i=0;i<4;i++) a[i]=Ls[t][ty+16*i];
#pragma unroll
        for(int j=0;j<4;j++) b[j]=Us[t][tx+16*j];
#pragma unroll
        for(int i=0;i<4;i++)
#pragma unroll
            for(int j=0;j<4;j++) acc[i][j] += a[i]*b[j];
    }
#pragma unroll
    for(int i=0;i<4;i++)
#pragma unroll
        for(int j=0;j<4;j++){
            size_t offm = (size_t)(r0+ty+16*i)*N + (c0+tx+16*j);
            g_M[offm] -= acc[i][j];
        }
}

__global__ __launch_bounds__(256, 3) void k_lu(){
    __shared__ float sA[64][65];
    __shared__ float sB[64][65];
    __shared__ float sInv[64];
    __shared__ float sRow[64];
    __shared__ float sPiv[64];
    int bid = blockIdx.x;

    if(bid==0) d_ludiag(0, sRow, sPiv);
    gbar();

    for(int kb=0; kb<NKB-1; kb++){
        int nt = NKB-1-kb;   // trailing tiles per dim, >= 1
        // ---- phase 1: panel TRSM (2*nt tiles) ----
        if(bid < 2*nt){
            d_loadD(kb, sA, sInv);
            for(int it=bid; it<2*nt; it+=GRID_LU){
                int t = kb+1 + (it>>1);
                if(it&1) d_trsmU(kb, t, sA, sB);
                else     d_trsmL(kb, t, sA, sInv);
            }
        }
        gbar();
        // ---- phase 2: trailing update + lookahead diag ----
        if(bid==0){
            d_gemm(kb, kb+1, kb+1, sA, sB);   // corner first
            __threadfence_block();
            d_ludiag(kb+1, sRow, sPiv);       // overlapped with other blocks' gemm
        } else {
            int tot = nt*nt - 1;              // all but the corner
            for(int it=bid-1; it<tot; it+=GRID_LU-1){
                int idx = it + 1;             // skip corner (idx 0)
                int i = kb+1 + idx/nt;
                int j = kb+1 + idx%nt;
                d_gemm(kb, i, j, sA, sB);
            }
        }
        gbar();
    }
}

// ---------------- finalize ----------------
__global__ void k_final(const int* __restrict__ troot, float* __restrict__ out){
    int root = troot[0];
    float gold = g_rs[root] + (float)g_acc[0];
    bool pos = ((g_neg & 1)==0) && (g_bad==0);
    float logdet = pos ? (float)g_acc[2] : __int_as_float(0x7fc00000);
    float notnan = (!isnan(gold) && !isnan(logdet)) ? 1.f : 0.f;
    float mask = (gold <= logdet*notnan) ? 1.f : 0.f;
    float loss = (logdet - gold)*mask;
    if(isnan(loss)) loss = 0.f;
    out[0] = 0.25f*loss + (float)g_acc[1];
}

// ---------------- launch ----------------
extern "C" void kernel_launch(void* const* d_in, const int* in_sizes, int n_in,
                              void* d_out, int out_size){
    const float* X     = (const float*)d_in[0];
    const float* Ladj  = (const float*)d_in[1];
    const float* Radj  = (const float*)d_in[2];
    const float* Wb    = (const float*)d_in[3];
    const float* bb    = (const float*)d_in[4];
    const float* Wh    = (const float*)d_in[5];
    const float* Wd    = (const float*)d_in[6];
    const float* Wr1   = (const float*)d_in[7];
    const float* br1   = (const float*)d_in[8];
    const float* Wr2   = (const float*)d_in[9];
    const float* br2   = (const float*)d_in[10];
    const float* Wrel1 = (const float*)d_in[11];
    const float* brel1 = (const float*)d_in[12];
    const float* Wrel2 = (const float*)d_in[13];
    const float* brel2 = (const float*)d_in[14];
    const int*   chl   = (const int*)d_in[15];
    const int*   par   = (const int*)d_in[16];
    const int*   rels  = (const int*)d_in[17];
    const int*   troot = (const int*)d_in[18];

    k_init<<<N/256, 256>>>();
    k_computeU<<<dim3(H/64, N/64, 2), 256>>>(X, Wb);
    k_headdep<<<N, 256>>>(X, Wh, Wd, Wr1, br1, Wr2, br2);
    k_compatA<<<dim3(N/64, N/64), 256>>>(X, bb);
    k_colsum<<<dim3(N/256, 8), 256>>>();
    k_buildM<<<dim3(N/256, N), 256>>>();
    k_gold<<<NEDGE, 256>>>(X, Ladj, Radj, bb, par, chl);
    k_ce<<<NEDGE, 256>>>(X, Wrel1, brel1, Wrel2, brel2, par, chl, rels);

    k_lu<<<GRID_LU, 256>>>();

    k_final<<<1,1>>>(troot, (float*)d_out);
}

// round 17
// speedup vs baseline: 1.3336x; 1.0351x over previous
#include <cuda_runtime.h>
#include <math.h>

#define N 3072
#define H 256
#define NEDGE (N-1)
#define NREL 18
#define NB 64
#define NKB (N/NB)   // 48
#define GRID_LU 444  // 3 blocks/SM * 148 SMs, co-residency forced by __launch_bounds__(256,3)

// ---------------- device scratch (no allocations allowed) ----------------
__device__ float g_U[2*N*H];      // U_k = X @ W_bilin[k]
__device__ float g_hd[2*N];       // head scores per k
__device__ float g_dp[2*N];       // dep scores per k
__device__ float g_rs[N];         // root scores
__device__ float g_A[N*N];        // A = exp(c0)+exp(c1)
__device__ float g_M[N*N];        // permuted Laplacian -> LU in place
__device__ float g_colsum[N];     // off-diagonal column sums of A
__device__ double g_acc[3];       // 0: gold(edges), 1: ce, 2: log|det| sum
__device__ int g_neg;             // negative-pivot parity count
__device__ int g_bad;             // zero/nan/inf pivot flag
__device__ unsigned g_sync_cnt;
__device__ unsigned g_sync_gen;
__device__ int g_Lflag[NKB];      // epoch stamp: L-panel tile t solved for iter kb -> kb+1
__device__ int g_Uflag[NKB];      // epoch stamp: U-panel tile t solved for iter kb -> kb+1

__device__ __forceinline__ float gelu_exact(float v){
    return 0.5f * v * (1.0f + erff(v * 0.70710678118654752f));
}

// ---------------- init ----------------
__global__ void k_init(){
    int j = blockIdx.x*256 + threadIdx.x;
    if(j < N) g_colsum[j] = 0.f;
    if(blockIdx.x==0 && threadIdx.x < NKB){
        g_Lflag[threadIdx.x] = 0;
        g_Uflag[threadIdx.x] = 0;
    }
    if(blockIdx.x==0 && threadIdx.x == 0){
        g_acc[0]=0.0; g_acc[1]=0.0; g_acc[2]=0.0;
        g_neg=0; g_bad=0;
        g_sync_cnt=0u; g_sync_gen=0u;
    }
}

// ---------------- U_k = X @ W_bilin[k]  (grid: (H/64, N/64, 2)) ----------------
__global__ __launch_bounds__(256) void k_computeU(const float* __restrict__ X,
                                                  const float* __restrict__ Wb){
    int kk = blockIdx.z;
    const float* W = Wb + kk*H*H;
    float* Uo = g_U + kk*N*H;
    __shared__ float As[32][65];
    __shared__ float Bs[32][65];
    int tid = threadIdx.x;
    int tx = tid & 15, ty = tid >> 4;
    int r0 = blockIdx.y*64, c0 = blockIdx.x*64;
    float acc[4][4];
#pragma unroll
    for(int i=0;i<4;i++)
#pragma unroll
        for(int j=0;j<4;j++) acc[i][j]=0.f;
    for(int h0=0; h0<H; h0+=32){
#pragma unroll
        for(int l=0;l<8;l++){
            int idx = l*256+tid;
            int i = idx>>5, t = idx&31;
            As[t][i] = X[(r0+i)*H + h0 + t];
        }
#pragma unroll
        for(int l=0;l<8;l++){
            int idx = l*256+tid;
            int t = idx>>6, c = idx&63;
            Bs[t][c] = W[(h0+t)*H + c0 + c];
        }
        __syncthreads();
#pragma unroll 8
        for(int t=0;t<32;t++){
            float a[4], b[4];
#pragma unroll
            for(int i=0;i<4;i++) a[i]=As[t][ty+16*i];
#pragma unroll
            for(int j=0;j<4;j++) b[j]=Bs[t][tx+16*j];
#pragma unroll
            for(int i=0;i<4;i++)
#pragma unroll
                for(int j=0;j<4;j++) acc[i][j] += a[i]*b[j];
        }
        __syncthreads();
    }
#pragma unroll
    for(int i=0;i<4;i++)
#pragma unroll
        for(int j=0;j<4;j++)
            Uo[(r0+ty+16*i)*H + c0+tx+16*j] = acc[i][j];
}

// ---------------- head/dep scores + root scores (grid: N blocks) ----------------
__global__ __launch_bounds__(256) void k_headdep(const float* __restrict__ X,
        const float* __restrict__ Wh, const float* __restrict__ Wd,
        const float* __restrict__ Wr1, const float* __restrict__ br1,
        const float* __restrict__ Wr2, const float* __restrict__ br2){
    int i = blockIdx.x, t = threadIdx.x;
    __shared__ float xs[H];
    __shared__ float red[256];
    xs[t] = X[i*H+t];
    __syncthreads();
    float acc = 0.f;
#pragma unroll 8
    for(int d=0; d<H; d++) acc += xs[d]*Wr1[d*H+t];
    acc += br1[t];
    float g = gelu_exact(acc);
    float vals[5];
    vals[0] = g*Wr2[t];
    vals[1] = xs[t]*Wh[t];
    vals[2] = xs[t]*Wh[H+t];
    vals[3] = xs[t]*Wd[t];
    vals[4] = xs[t]*Wd[H+t];
    float out[5];
#pragma unroll
    for(int v=0; v<5; v++){
        red[t]=vals[v]; __syncthreads();
        for(int s=128;s>0;s>>=1){ if(t<s) red[t]+=red[t+s]; __syncthreads(); }
        out[v]=red[0]; __syncthreads();
    }
    if(t==0){
        g_rs[i]   = out[0] + br2[0];
        g_hd[i]   = out[1];
        g_hd[N+i] = out[2];
        g_dp[i]   = out[3];
        g_dp[N+i] = out[4];
    }
}

// ---------------- A[i][j] = exp(c0)+exp(c1)  (grid: (N/64, N/64)) ----------------
__global__ __launch_bounds__(256) void k_compatA(const float* __restrict__ X,
                                                 const float* __restrict__ bb){
    __shared__ float U0s[32][65], U1s[32][65], Xs[32][65];
    int tid=threadIdx.x, tx=tid&15, ty=tid>>4;
    int r0=blockIdx.y*64, c0=blockIdx.x*64;
    float a0[4][4], a1[4][4];
#pragma unroll
    for(int i=0;i<4;i++)
#pragma unroll
        for(int j=0;j<4;j++){ a0[i][j]=0.f; a1[i][j]=0.f; }
    const float* U0 = g_U;
    const float* U1 = g_U + N*H;
    for(int d0=0; d0<H; d0+=32){
#pragma unroll
        for(int l=0;l<8;l++){
            int idx=l*256+tid; int i=idx>>5, t=idx&31;
            U0s[t][i] = U0[(r0+i)*H + d0+t];
            U1s[t][i] = U1[(r0+i)*H + d0+t];
            Xs[t][i]  = X [(c0+i)*H + d0+t];
        }
        __syncthreads();
#pragma unroll 8
        for(int t=0;t<32;t++){
            float x0[4],x1[4],b[4];
#pragma unroll
            for(int i=0;i<4;i++){ x0[i]=U0s[t][ty+16*i]; x1[i]=U1s[t][ty+16*i]; }
#pragma unroll
            for(int j=0;j<4;j++) b[j]=Xs[t][tx+16*j];
#pragma unroll
            for(int i=0;i<4;i++)
#pragma unroll
                for(int j=0;j<4;j++){ a0[i][j]+=x0[i]*b[j]; a1[i][j]+=x1[i]*b[j]; }
        }
        __syncthreads();
    }
    float bb0=bb[0], bb1=bb[1];
#pragma unroll
    for(int i=0;i<4;i++){
        int r = r0+ty+16*i;
        float h0=g_hd[r], h1=g_hd[N+r];
#pragma unroll
        for(int j=0;j<4;j++){
            int c = c0+tx+16*j;
            float c0v = a0[i][j] + bb0 + h0 + g_dp[c];
            float c1v = a1[i][j] + bb1 + h1 + g_dp[N+c];
            g_A[r*N+c] = expf(c0v) + expf(c1v);
        }
    }
}

// ---------------- off-diagonal column sums (grid: (N/256, 8)) ----------------
__global__ void k_colsum(){
    int j = blockIdx.x*256 + threadIdx.x;
    int i0 = blockIdx.y * (N/8);
    float s = 0.f;
    for(int i=i0; i<i0+(N/8); i++){
        if(i!=j) s += g_A[(size_t)i*N+j];
    }
    atomicAdd(&g_colsum[j], s);
}

// ---------------- build permuted Laplacian M (grid: (N/256, N)) ----------------
__global__ void k_buildM(){
    int j = blockIdx.x*256 + threadIdx.x;
    int i = blockIdx.y;
    int oi = (i==N-1) ? 0 : (i+1);
    int oj = (j==N-1) ? 0 : (j+1);
    float v;
    if(oi==0)          v = expf(g_rs[oj]);
    else if(oi==oj)    v = g_colsum[oj];
    else               v = -g_A[(size_t)oi*N+oj];
    g_M[(size_t)i*N+j] = v;
}

// ---------------- gold: gather compat at edges ----------------
__global__ __launch_bounds__(256) void k_gold(const float* __restrict__ X,
        const float* __restrict__ Ladj, const float* __restrict__ Radj,
        const float* __restrict__ bb,
        const int* __restrict__ par, const int* __restrict__ chl){
    int e = blockIdx.x, t = threadIdx.x;
    int p = par[e], c = chl[e];
    __shared__ float red[256];
    float xc = X[c*H+t];
    float s0 = g_U[p*H+t]*xc;
    float s1 = g_U[N*H + p*H+t]*xc;
    red[t]=s0; __syncthreads();
    for(int s=128;s>0;s>>=1){ if(t<s) red[t]+=red[t+s]; __syncthreads(); }
    float r0v = red[0]; __syncthreads();
    red[t]=s1; __syncthreads();
    for(int s=128;s>0;s>>=1){ if(t<s) red[t]+=red[t+s]; __syncthreads(); }
    float r1v = red[0];
    if(t==0){
        float c0v = r0v + bb[0] + g_hd[p]   + g_dp[c];
        float c1v = r1v + bb[1] + g_hd[N+p] + g_dp[N+c];
        float lf = Ladj[(size_t)p*N+c];
        float rf = Radj[(size_t)p*N+c];
        atomicAdd(&g_acc[0], (double)(lf*c0v + rf*c1v));
    }
}

// ---------------- relation CE loss ----------------
__global__ __launch_bounds__(256) void k_ce(const float* __restrict__ X,
        const float* __restrict__ Wrel1, const float* __restrict__ brel1,
        const float* __restrict__ Wrel2, const float* __restrict__ brel2,
        const int* __restrict__ par, const int* __restrict__ chl,
        const int* __restrict__ rels){
    int e = blockIdx.x, t = threadIdx.x;
    int p = par[e], c = chl[e];
    __shared__ float xp[H], xc[H], hs[H];
    __shared__ float lg[NREL];
    xp[t] = X[p*H+t];
    xc[t] = X[c*H+t];
    __syncthreads();
    float acc = brel1[t];
#pragma unroll 8
    for(int d=0; d<H; d++) acc += xp[d]*Wrel1[d*H + t];
#pragma unroll 8
    for(int d=0; d<H; d++) acc += xc[d]*Wrel1[(H+d)*H + t];
    hs[t] = gelu_exact(acc);
    __syncthreads();
    if(t < NREL){
        float a = brel2[t];
        for(int u=0; u<H; u++) a += hs[u]*Wrel2[u*NREL + t];
        lg[t] = a;
    }
    __syncthreads();
    if(t==0){
        float mx = lg[0];
#pragma unroll
        for(int r=1;r<NREL;r++) mx = fmaxf(mx, lg[r]);
        float s = 0.f;
#pragma unroll
        for(int r=0;r<NREL;r++) s += expf(lg[r]-mx);
        float lse = mx + logf(s);
        int rl = rels[e];
        atomicAdd(&g_acc[1], (double)(lse - lg[rl]));
    }
}

// ================= persistent LU =================

__device__ __forceinline__ void gbar(){
    __syncthreads();
    if(threadIdx.x==0){
        __threadfence();
        volatile unsigned* genp = (volatile unsigned*)&g_sync_gen;
        unsigned gen = *genp;
        unsigned arrived = atomicAdd(&g_sync_cnt, 1u);
        if(arrived == GRID_LU-1u){
            g_sync_cnt = 0u;
            __threadfence();
            *genp = gen + 1u;
        } else {
            while(*genp == gen) __nanosleep(64);
            __threadfence();
        }
    }
    __syncthreads();
}

// 64x64 diagonal LU, register-resident; called by block 0 only (all 256 threads)
__device__ void d_ludiag(int kb, float* rowbuf, float* pivbuf){
    int k0 = kb*64;
    int tid = threadIdx.x;
    int r = tid>>2, cq = tid&3;
    float v[16];
    __syncthreads();
    const float4* gp = (const float4*)(g_M + (size_t)(k0+r)*N + k0);
    float4 a0 = gp[cq*4+0], a1 = gp[cq*4+1], a2 = gp[cq*4+2], a3 = gp[cq*4+3];
    v[0]=a0.x; v[1]=a0.y; v[2]=a0.z; v[3]=a0.w;
    v[4]=a1.x; v[5]=a1.y; v[6]=a1.z; v[7]=a1.w;
    v[8]=a2.x; v[9]=a2.y; v[10]=a2.z; v[11]=a2.w;
    v[12]=a3.x; v[13]=a3.y; v[14]=a3.z; v[15]=a3.w;
    __syncthreads();
#pragma unroll
    for(int j=0;j<64;j++){
        if(r==j){
#pragma unroll
            for(int ci=0;ci<16;ci++) rowbuf[(cq<<4)+ci] = v[ci];
        }
        __syncthreads();
        float piv = rowbuf[j];
        if(tid==0) pivbuf[j] = piv;
        float invp = 1.0f/piv;
        float l = __shfl_sync(0xffffffffu, v[j&15], ((r&7)<<2)|(j>>4)) * invp;
        if(r>j){
            if(cq == (j>>4)) v[j&15] = l;
#pragma unroll
            for(int ci=0;ci<16;ci++){
                int c = (cq<<4)+ci;
                if(c>j) v[ci] -= l*rowbuf[c];
            }
        }
        __syncthreads();
    }
    float4 o;
    float4* op = (float4*)(g_M + (size_t)(k0+r)*N + k0);
    o.x=v[0]; o.y=v[1]; o.z=v[2]; o.w=v[3];   op[cq*4+0]=o;
    o.x=v[4]; o.y=v[5]; o.z=v[6]; o.w=v[7];   op[cq*4+1]=o;
    o.x=v[8]; o.y=v[9]; o.z=v[10]; o.w=v[11]; op[cq*4+2]=o;
    o.x=v[12]; o.y=v[13]; o.z=v[14]; o.w=v[15]; op[cq*4+3]=o;
    __syncthreads();
    if(tid==0){
        double lacc = 0.0; int neg=0, bad=0;
        for(int j=0;j<64;j++){
            float p = pivbuf[j];
            if(!(fabsf(p) > 0.f) || isinf(p)) bad = 1;
            if(p < 0.f) neg ^= 1;
            lacc += log(fabs((double)p));
        }
        g_acc[2] += lacc;
        g_neg += neg;
        if(bad) g_bad = 1;
    }
    __syncthreads();
}

// load diagonal tile D (row-major, stride 65) + reciprocals
__device__ void d_loadD(int kb, float* D, float* invd){
    int tid = threadIdx.x, k0 = kb*64;
    __syncthreads();
#pragma unroll
    for(int l=0;l<16;l++){
        int idx=l*256+tid; int i=idx>>6, j=idx&63;
        D[i*65+j] = g_M[(size_t)(k0+i)*N + k0+j];
    }
    __syncthreads();
    if(tid<64) invd[tid] = 1.0f/D[tid*65+tid];
    __syncthreads();
}

// L21 tile: solve X * U11 = A21 for 64 rows at tile*64 (register-resident)
__device__ void d_trsmL(int kb, int tile, const float* D, const float* invd){
    int k0 = kb*64, row0 = tile*64;
    int tid = threadIdx.x;
    int r = tid>>2, cq = tid&3;
    float v[16];
    const float4* gp = (const float4*)(g_M + (size_t)(row0+r)*N + k0);
    float4 a0=gp[cq*4+0], a1=gp[cq*4+1], a2=gp[cq*4+2], a3=gp[cq*4+3];
    v[0]=a0.x; v[1]=a0.y; v[2]=a0.z; v[3]=a0.w;
    v[4]=a1.x; v[5]=a1.y; v[6]=a1.z; v[7]=a1.w;
    v[8]=a2.x; v[9]=a2.y; v[10]=a2.z; v[11]=a2.w;
    v[12]=a3.x; v[13]=a3.y; v[14]=a3.z; v[15]=a3.w;
#pragma unroll
    for(int j=0;j<64;j++){
        float xj = __shfl_sync(0xffffffffu, v[j&15], ((r&7)<<2)|(j>>4));
        xj *= invd[j];
        if(cq == (j>>4)) v[j&15] = xj;
#pragma unroll
        for(int ci=0;ci<16;ci++){
            int c = (cq<<4)+ci;
            if(c>j) v[ci] -= xj*D[j*65+c];
        }
    }
    float4 o;
    float4* op = (float4*)(g_M + (size_t)(row0+r)*N + k0);
    o.x=v[0]; o.y=v[1]; o.z=v[2]; o.w=v[3];   op[cq*4+0]=o;
    o.x=v[4]; o.y=v[5]; o.z=v[6]; o.w=v[7];   op[cq*4+1]=o;
    o.x=v[8]; o.y=v[9]; o.z=v[10]; o.w=v[11]; op[cq*4+2]=o;
    o.x=v[12]; o.y=v[13]; o.z=v[14]; o.w=v[15]; op[cq*4+3]=o;
}

// U12 tile: solve L11 * X = A12 for 64 cols at tile*64; stages through S
__device__ void d_trsmU(int kb, int tile, const float* D, float* S){
    int k0 = kb*64, col0 = tile*64;
    int tid = threadIdx.x;
    __syncthreads();
#pragma unroll
    for(int l=0;l<16;l++){
        int idx=l*256+tid; int i=idx>>6, j=idx&63;
        S[i*65+j] = g_M[(size_t)(k0+i)*N + col0+j];
    }
    __syncthreads();
    int c = tid>>2, rq = tid&3;
    float v[16];
#pragma unroll
    for(int ri=0;ri<16;ri++) v[ri] = S[((rq<<4)+ri)*65 + c];
    __syncthreads();
#pragma unroll
    for(int t=0;t<64;t++){
        float xt = __shfl_sync(0xffffffffu, v[t&15], ((c&7)<<2)|(t>>4));
#pragma unroll
        for(int ri=0;ri<16;ri++){
            int rr = (rq<<4)+ri;
            if(rr>t) v[ri] -= D[rr*65+t]*xt;
        }
    }
#pragma unroll
    for(int ri=0;ri<16;ri++) S[((rq<<4)+ri)*65 + c] = v[ri];
    __syncthreads();
#pragma unroll
    for(int l=0;l<16;l++){
        int idx=l*256+tid; int i=idx>>6, j=idx&63;
        g_M[(size_t)(k0+i)*N + col0+j] = S[i*65+j];
    }
    __syncthreads();
}

// 64x64 corner tile: C(ti,tj) -= L(ti,kb) @ U(kb,tj)   (block 0 only)
__device__ void d_gemm64(int kb, int ti, int tj, float* pool){
    float* Ls = pool;         // [64][65] as [t][row]
    float* Us = pool + 4160;  // [64][65] as [t][col]
    int k0 = kb*64, r0 = ti*64, c0 = tj*64;
    int tid = threadIdx.x, tx = tid&15, ty = tid>>4;
    __syncthreads();
#pragma unroll
    for(int l=0;l<16;l++){
        int idx=l*256+tid; int i=idx>>6, t=idx&63;
        Ls[t*65+i] = g_M[(size_t)(r0+i)*N + k0+t];
        Us[i*65+t] = g_M[(size_t)(k0+i)*N + c0+t];
    }
    __syncthreads();
    float acc[4][4];
#pragma unroll
    for(int i=0;i<4;i++)
#pragma unroll
        for(int j=0;j<4;j++) acc[i][j]=0.f;
#pragma unroll 8
    for(int t=0;t<64;t++){
        float a[4],b[4];
#pragma unroll
        for(int i=0;i<4;i++) a[i]=Ls[t*65+ty+16*i];
#pragma unroll
        for(int j=0;j<4;j++) b[j]=Us[t*65+tx+16*j];
#pragma unroll
        for(int i=0;i<4;i++)
#pragma unroll
            for(int j=0;j<4;j++) acc[i][j] += a[i]*b[j];
    }
#pragma unroll
    for(int i=0;i<4;i++)
#pragma unroll
        for(int j=0;j<4;j++){
            size_t offm = (size_t)(r0+ty+16*i)*N + (c0+tx+16*j);
            g_M[offm] -= acc[i][j];
        }
}

// 128x64 trailing tile pair: rows (i0, i0+1) x col j0, k staged in two 32-halves
__device__ void d_gemm128(int kb, int i0, int j0, bool do_top, bool do_bot, float* pool){
    float* Lt = pool;          // [32][65] [t][row] top 64 rows
    float* Lb = pool + 2080;   // [32][65] bottom 64 rows
    float* Us = pool + 4160;   // [32][65] [t][col]
    int k0 = kb*64, r0 = i0*64, rb = r0+64, c0 = j0*64;
    int tid = threadIdx.x, tx = tid&15, ty = tid>>4;
    float acc[8][4];
#pragma unroll
    for(int i=0;i<8;i++)
#pragma unroll
        for(int j=0;j<4;j++) acc[i][j]=0.f;
    for(int kk=0; kk<64; kk+=32){
        __syncthreads();
#pragma unroll
        for(int l=0;l<8;l++){
            int idx=l*256+tid; int i=idx>>5, t=idx&31;
            Lt[t*65+i] = g_M[(size_t)(r0+i)*N + k0+kk+t];
            Lb[t*65+i] = do_bot ? g_M[(size_t)(rb+i)*N + k0+kk+t] : 0.f;
        }
#pragma unroll
        for(int l=0;l<8;l++){
            int idx=l*256+tid; int t=idx>>6, c=idx&63;
            Us[t*65+c] = g_M[(size_t)(k0+kk+t)*N + c0+c];
        }
        __syncthreads();
#pragma unroll 8
        for(int t=0;t<32;t++){
            float a[8], b[4];
#pragma unroll
            for(int i=0;i<4;i++){ a[i]=Lt[t*65+ty+16*i]; a[4+i]=Lb[t*65+ty+16*i]; }
#pragma unroll
            for(int j=0;j<4;j++) b[j]=Us[t*65+tx+16*j];
#pragma unroll
            for(int i=0;i<8;i++)
#pragma unroll
                for(int j=0;j<4;j++) acc[i][j] += a[i]*b[j];
        }
    }
    if(do_top){
#pragma unroll
        for(int i=0;i<4;i++)
#pragma unroll
            for(int j=0;j<4;j++){
                size_t offm = (size_t)(r0+ty+16*i)*N + (c0+tx+16*j);
                g_M[offm] -= acc[i][j];
            }
    }
    if(do_bot){
#pragma unroll
        for(int i=0;i<4;i++)
#pragma unroll
            for(int j=0;j<4;j++){
                size_t offm = (size_t)(rb+ty+16*i)*N + (c0+tx+16*j);
                g_M[offm] -= acc[4+i][j];
            }
    }
}

__global__ __launch_bounds__(256, 3) void k_lu(){
    __shared__ float pool[8384];   // 33.5 KB carved workspace
    int bid = blockIdx.x, tid = threadIdx.x;

    if(bid==0) d_ludiag(0, pool, pool+64);
    gbar();

    for(int kb=0; kb<NKB-1; kb++){
        int nt = NKB-1-kb;   // trailing tiles per dim, >= 1

        // ---- panel TRSM (data-driven release; blocks 1..2nt) ----
        if(bid>=1 && bid<=2*nt){
            d_loadD(kb, pool, pool+4160);
            int it = bid-1;
            int t = kb+1 + (it>>1);
            if(it&1) d_trsmU(kb, t, pool, pool+4224);
            else     d_trsmL(kb, t, pool, pool+4160);
            __syncthreads();
            if(tid==0){
                __threadfence();
                if(it&1) *(volatile int*)&g_Uflag[t] = kb+1;
                else     *(volatile int*)&g_Lflag[t] = kb+1;
            }
        }

        if(bid==0){
            // corner gemm + lookahead diag factorization
            if(tid==0){
                while(*(volatile int*)&g_Lflag[kb+1] != kb+1) __nanosleep(32);
                while(*(volatile int*)&g_Uflag[kb+1] != kb+1) __nanosleep(32);
                __threadfence();
            }
            __syncthreads();
            d_gemm64(kb, kb+1, kb+1, pool);
            d_ludiag(kb+1, pool, pool+64);
        } else {
            // trailing update, 128x64 tile pairs, flag-gated
            int RG = (nt+1)>>1;
            int TG = RG*nt;
            for(int tt=bid-1; tt<TG; tt+=GRID_LU-1){
                int rg = tt/nt, j = tt - rg*nt;
                int i0 = kb+1 + 2*rg;
                int j0 = kb+1 + j;
                bool do_top = !(rg==0 && j==0);     // corner handled by block 0
                bool do_bot = (2*rg+1 < nt);
                if(tid==0){
                    if(do_top) while(*(volatile int*)&g_Lflag[i0]   != kb+1) __nanosleep(32);
                    if(do_bot) while(*(volatile int*)&g_Lflag[i0+1] != kb+1) __nanosleep(32);
                    while(*(volatile int*)&g_Uflag[j0] != kb+1) __nanosleep(32);
                    __threadfence();
                }
                __syncthreads();
                d_gemm128(kb, i0, j0, do_top, do_bot, pool);
            }
        }
        gbar();
    }
}

// ---------------- finalize ----------------
__global__ void k_final(const int* __restrict__ troot, float* __restrict__ out){
    int root = troot[0];
    float gold = g_rs[root] + (float)g_acc[0];
    bool pos = ((g_neg & 1)==0) && (g_bad==0);
    float logdet = pos ? (float)g_acc[2] : __int_as_float(0x7fc00000);
    float notnan = (!isnan(gold) && !isnan(logdet)) ? 1.f : 0.f;
    float mask = (gold <= logdet*notnan) ? 1.f : 0.f;
    float loss = (logdet - gold)*mask;
    if(isnan(loss)) loss = 0.f;
    out[0] = 0.25f*loss + (float)g_acc[1];
}

// ---------------- launch ----------------
extern "C" void kernel_launch(void* const* d_in, const int* in_sizes, int n_in,
                              void* d_out, int out_size){
    const float* X     = (const float*)d_in[0];
    const float* Ladj  = (const float*)d_in[1];
    const float* Radj  = (const float*)d_in[2];
    const float* Wb    = (const float*)d_in[3];
    const float* bb    = (const float*)d_in[4];
    const float* Wh    = (const float*)d_in[5];
    const float* Wd    = (const float*)d_in[6];
    const float* Wr1   = (const float*)d_in[7];
    const float* br1   = (const float*)d_in[8];
    const float* Wr2   = (const float*)d_in[9];
    const float* br2   = (const float*)d_in[10];
    const float* Wrel1 = (const float*)d_in[11];
    const float* brel1 = (const float*)d_in[12];
    const float* Wrel2 = (const float*)d_in[13];
    const float* brel2 = (const float*)d_in[14];
    const int*   chl   = (const int*)d_in[15];
    const int*   par   = (const int*)d_in[16];
    const int*   rels  = (const int*)d_in[17];
    const int*   troot = (const int*)d_in[18];

    k_init<<<N/256, 256>>>();
    k_computeU<<<dim3(H/64, N/64, 2), 256>>>(X, Wb);
    k_headdep<<<N, 256>>>(X, Wh, Wd, Wr1, br1, Wr2, br2);
    k_compatA<<<dim3(N/64, N/64), 256>>>(X, bb);
    k_colsum<<<dim3(N/256, 8), 256>>>();
    k_buildM<<<dim3(N/256, N), 256>>>();
    k_gold<<<NEDGE, 256>>>(X, Ladj, Radj, bb, par, chl);
    k_ce<<<NEDGE, 256>>>(X, Wrel1, brel1, Wrel2, brel2, par, chl, rels);

    k_lu<<<GRID_LU, 256>>>();

    k_final<<<1,1>>>(troot, (float*)d_out);
}